// round 9
// baseline (speedup 1.0000x reference)
#include <cuda_runtime.h>
#include <cuda_fp16.h>
#include <stdint.h>

// Problem constants (fixed by reference: B=32, N=4096, D=128, E=24576)
#define BB 32
#define NN 4096
#define DD 128
#define EE 24576
#define BN (BB * NN)
#define NCHUNK 24          // EE / 1024

// Scratch (device globals: no allocation allowed in kernel_launch)
__device__ int   g_cnt[NCHUNK * NN];    // per-(chunk, node) histogram
__device__ int   g_offsets[NN + 1];
__device__ int   g_srcs[EE];            // src node per CSR slot (edge-id order)
__device__ int   g_dsts[EE];            // dst node per CSR slot
__device__ float g_ssrc[BN];
__device__ float g_sdst[BN];            // includes bias
__device__ float g_att[(size_t)BB * EE];     // sigmoid gate per (b, slot)
__device__ uint2 g_x16[(size_t)BN * 32];     // x in half precision (33 MB), 4 halves/lane

// ---------------------------------------------------------------------------
// kA: per-chunk histogram. Block c owns edges [1024c, 1024c+1024).
// ---------------------------------------------------------------------------
__global__ void kA_hist(const int* __restrict__ dst) {
    __shared__ int h[NN];
    int c = blockIdx.x, t = threadIdx.x;
    #pragma unroll
    for (int i = t; i < NN; i += 1024) h[i] = 0;
    __syncthreads();
    atomicAdd(&h[dst[c * 1024 + t]], 1);
    __syncthreads();
    #pragma unroll
    for (int i = t; i < NN; i += 1024) g_cnt[c * NN + i] = h[i];
}

// ---------------------------------------------------------------------------
// k_build2: fused totals + scan + per-chunk bases + deterministic scatter.
// 24 blocks; block c scatters chunk c. Output slots are in exact edge-id
// order within each dst bucket -> deterministic accumulation downstream.
// ---------------------------------------------------------------------------
__global__ void k_build2(const int* __restrict__ src, const int* __restrict__ dst) {
    __shared__ int offs[NN];       // exclusive offsets -> then cursors for chunk c
    __shared__ int part[1024];
    int c = blockIdx.x, t = threadIdx.x;
    int base = t * 4;

    // totals + prefix-below-c for this thread's 4 nodes (coalesced loads)
    int tot[4] = {0, 0, 0, 0};
    int pre[4] = {0, 0, 0, 0};
    #pragma unroll
    for (int cc = 0; cc < NCHUNK; cc++) {
        #pragma unroll
        for (int k = 0; k < 4; k++) {
            int v = g_cnt[cc * NN + base + k];
            tot[k] += v;
            if (cc < c) pre[k] += v;
        }
    }

    // block-wide exclusive scan of totals
    int s = tot[0] + tot[1] + tot[2] + tot[3];
    part[t] = s;
    __syncthreads();
    for (int off = 1; off < 1024; off <<= 1) {
        int add = (t >= off) ? part[t - off] : 0;
        __syncthreads();
        part[t] += add;
        __syncthreads();
    }
    int run = part[t] - s;
    #pragma unroll
    for (int k = 0; k < 4; k++) {
        if (c == 0) g_offsets[base + k] = run;
        offs[base + k] = run + pre[k];   // this chunk's cursor for node base+k
        run += tot[k];
    }
    if (c == 0 && t == 1023) g_offsets[NN] = run;  // == EE
    __syncthreads();

    // deterministic scatter of chunk c: in-warp rank via match_any,
    // in-block order via 32 serialized warp rounds, cross-chunk via pre[].
    int e  = c * 1024 + t;
    int d  = dst[e];
    int sv = src[e];
    unsigned mask = __match_any_sync(0xFFFFFFFFu, d);
    int lane     = t & 31;
    int lanerank = __popc(mask & ((1u << lane) - 1));
    int cntm     = __popc(mask);
    int leader   = __ffs(mask) - 1;
    int wid      = t >> 5;

    int bpos = 0;
    #pragma unroll
    for (int w = 0; w < 32; w++) {
        if (wid == w && lane == leader) {
            bpos = offs[d];
            offs[d] = bpos + cntm;
        }
        __syncthreads();
    }
    bpos = __shfl_sync(0xFFFFFFFFu, bpos, leader);
    g_srcs[bpos + lanerank] = sv;
    g_dsts[bpos + lanerank] = d;
}

// ---------------------------------------------------------------------------
// Per-node projections + fp16 staging. One warp per row; each lane owns one
// float4. Writes: ssrc/sdst (dot products) and g_x16 (half-converted x row,
// coalesced 256B/warp) — x is streamed once, so conversion is nearly free.
// ---------------------------------------------------------------------------
__global__ void k_dots(const float4* __restrict__ x4, const float4* __restrict__ W4,
                       const float* __restrict__ bias) {
    int wid  = (blockIdx.x * blockDim.x + threadIdx.x) >> 5;   // row in [0, B*N)
    int lane = threadIdx.x & 31;
    float4 xr = x4[(size_t)wid * 32 + lane];
    float4 ws = W4[lane];
    float4 wd = W4[32 + lane];

    // fp16 staged copy (4 halves per lane)
    __half2 h0 = __floats2half2_rn(xr.x, xr.y);
    __half2 h1 = __floats2half2_rn(xr.z, xr.w);
    uint2 pack;
    pack.x = *(unsigned int*)&h0;
    pack.y = *(unsigned int*)&h1;
    g_x16[(size_t)wid * 32 + lane] = pack;

    float a = xr.x * ws.x + xr.y * ws.y + xr.z * ws.z + xr.w * ws.w;
    float c = xr.x * wd.x + xr.y * wd.y + xr.z * wd.z + xr.w * wd.w;
    #pragma unroll
    for (int o = 16; o > 0; o >>= 1) {
        a += __shfl_xor_sync(0xFFFFFFFFu, a, o);
        c += __shfl_xor_sync(0xFFFFFFFFu, c, o);
    }
    if (lane == 0) {
        g_ssrc[wid] = a;
        g_sdst[wid] = c + bias[0];
    }
}

// ---------------------------------------------------------------------------
// Attention precompute: att[b, j] = sigmoid(ssrc[b, srcs[j]] + sdst[b, dsts[j]])
// Edge-parallel over (b, slot): 786k independent threads fully hide the
// random-gather + MUFU latency. Scores computed in full fp32.
// ---------------------------------------------------------------------------
__global__ void k_att() {
    int t = blockIdx.x * blockDim.x + threadIdx.x;   // [0, B*EE)
    int b = t / EE;
    int j = t - b * EE;
    int s = g_srcs[j];
    int n = g_dsts[j];
    float z = g_ssrc[b * NN + s] + g_sdst[b * NN + n];
    g_att[t] = 1.0f / (1.0f + __expf(-z));
}

// ---------------------------------------------------------------------------
// Main gather kernel: one warp per (b, n). Gathers HALF rows (256B/row, half
// the L2 traffic of fp32), accumulates in fp32, coalesced float4 stores.
// 2-edge unroll with dual accumulators.
// ---------------------------------------------------------------------------
__global__ void __launch_bounds__(256) k_main(float4* __restrict__ out4) {
    int w    = (blockIdx.x * blockDim.x + threadIdx.x) >> 5;   // (b,n) pair
    int lane = threadIdx.x & 31;
    int b = w >> 12;            // / NN
    int n = w & (NN - 1);
    const uint2*  xb   = g_x16 + ((size_t)b * NN) * 32;
    const float*  attb = g_att + (size_t)b * EE;
    int lo = g_offsets[n], hi = g_offsets[n + 1];

    float4 acc0 = make_float4(0.f, 0.f, 0.f, 0.f);
    float4 acc1 = make_float4(0.f, 0.f, 0.f, 0.f);
    int j = lo;
    for (; j + 1 < hi; j += 2) {
        int   s0 = g_srcs[j];
        int   s1 = g_srcs[j + 1];
        float a0 = attb[j];
        float a1 = attb[j + 1];
        uint2 r0 = xb[(size_t)s0 * 32 + lane];
        uint2 r1 = xb[(size_t)s1 * 32 + lane];
        float2 f00 = __half22float2(*(__half2*)&r0.x);
        float2 f01 = __half22float2(*(__half2*)&r0.y);
        float2 f10 = __half22float2(*(__half2*)&r1.x);
        float2 f11 = __half22float2(*(__half2*)&r1.y);
        acc0.x += f00.x * a0; acc0.y += f00.y * a0; acc0.z += f01.x * a0; acc0.w += f01.y * a0;
        acc1.x += f10.x * a1; acc1.y += f10.y * a1; acc1.z += f11.x * a1; acc1.w += f11.y * a1;
    }
    if (j < hi) {
        int   s0 = g_srcs[j];
        float a0 = attb[j];
        uint2 r0 = xb[(size_t)s0 * 32 + lane];
        float2 f00 = __half22float2(*(__half2*)&r0.x);
        float2 f01 = __half22float2(*(__half2*)&r0.y);
        acc0.x += f00.x * a0; acc0.y += f00.y * a0; acc0.z += f01.x * a0; acc0.w += f01.y * a0;
    }
    acc0.x += acc1.x; acc0.y += acc1.y; acc0.z += acc1.z; acc0.w += acc1.w;
    out4[(size_t)w * 32 + lane] = acc0;
}

// ---------------------------------------------------------------------------
// Launch
// ---------------------------------------------------------------------------
extern "C" void kernel_launch(void* const* d_in, const int* in_sizes, int n_in,
                              void* d_out, int out_size) {
    const float* x    = (const float*)d_in[0];   // (B, N, D) f32
    const int*   ei   = (const int*)d_in[1];     // (2, E)    i32
    const float* W    = (const float*)d_in[2];   // (1, 2D)   f32
    const float* bias = (const float*)d_in[3];   // (1,)      f32
    float* out = (float*)d_out;                  // (B, N, D) f32

    const int* src = ei;        // edge_index[0]
    const int* dst = ei + EE;   // edge_index[1]

    kA_hist<<<NCHUNK, 1024>>>(dst);
    k_build2<<<NCHUNK, 1024>>>(src, dst);
    k_dots<<<BN / 8, 256>>>((const float4*)x, (const float4*)W, bias);
    k_att<<<(BB * EE) / 256, 256>>>();
    k_main<<<BN / 8, 256>>>((float4*)out);
}

// round 10
// speedup vs baseline: 1.0409x; 1.0409x over previous
#include <cuda_runtime.h>
#include <cuda_fp16.h>
#include <stdint.h>

// Problem constants (fixed by reference: B=32, N=4096, D=128, E=24576)
#define BB 32
#define NN 4096
#define DD 128
#define EE 24576
#define BN (BB * NN)
#define NCHUNK 24          // EE / 1024

// Scratch (device globals: no allocation allowed in kernel_launch)
__device__ int   g_cnt[NCHUNK * NN];    // per-(chunk, node) histogram
__device__ int   g_offsets[NN + 1];
__device__ int   g_srcs[EE];            // src node per CSR slot (edge-id order)
__device__ int   g_dsts[EE];            // dst node per CSR slot
__device__ float g_ssrc[BN];
__device__ float g_sdst[BN];            // includes bias
__device__ float g_att[(size_t)BB * EE];     // sigmoid gate per (b, slot)
__device__ uint2 g_x16[(size_t)BN * 32];     // x in half precision (33 MB): row = 256B

// ---------------------------------------------------------------------------
// kA: per-chunk histogram. Block c owns edges [1024c, 1024c+1024).
// ---------------------------------------------------------------------------
__global__ void kA_hist(const int* __restrict__ dst) {
    __shared__ int h[NN];
    int c = blockIdx.x, t = threadIdx.x;
    #pragma unroll
    for (int i = t; i < NN; i += 1024) h[i] = 0;
    __syncthreads();
    atomicAdd(&h[dst[c * 1024 + t]], 1);
    __syncthreads();
    #pragma unroll
    for (int i = t; i < NN; i += 1024) g_cnt[c * NN + i] = h[i];
}

// ---------------------------------------------------------------------------
// k_build2: fused totals + scan + per-chunk bases + deterministic scatter.
// 24 blocks; block c scatters chunk c. Output slots are in exact edge-id
// order within each dst bucket -> deterministic accumulation downstream.
// ---------------------------------------------------------------------------
__global__ void k_build2(const int* __restrict__ src, const int* __restrict__ dst) {
    __shared__ int offs[NN];       // exclusive offsets -> then cursors for chunk c
    __shared__ int part[1024];
    int c = blockIdx.x, t = threadIdx.x;
    int base = t * 4;

    // totals + prefix-below-c for this thread's 4 nodes (coalesced loads)
    int tot[4] = {0, 0, 0, 0};
    int pre[4] = {0, 0, 0, 0};
    #pragma unroll
    for (int cc = 0; cc < NCHUNK; cc++) {
        #pragma unroll
        for (int k = 0; k < 4; k++) {
            int v = g_cnt[cc * NN + base + k];
            tot[k] += v;
            if (cc < c) pre[k] += v;
        }
    }

    // block-wide exclusive scan of totals
    int s = tot[0] + tot[1] + tot[2] + tot[3];
    part[t] = s;
    __syncthreads();
    for (int off = 1; off < 1024; off <<= 1) {
        int add = (t >= off) ? part[t - off] : 0;
        __syncthreads();
        part[t] += add;
        __syncthreads();
    }
    int run = part[t] - s;
    #pragma unroll
    for (int k = 0; k < 4; k++) {
        if (c == 0) g_offsets[base + k] = run;
        offs[base + k] = run + pre[k];   // this chunk's cursor for node base+k
        run += tot[k];
    }
    if (c == 0 && t == 1023) g_offsets[NN] = run;  // == EE
    __syncthreads();

    // deterministic scatter of chunk c: in-warp rank via match_any,
    // in-block order via 32 serialized warp rounds, cross-chunk via pre[].
    int e  = c * 1024 + t;
    int d  = dst[e];
    int sv = src[e];
    unsigned mask = __match_any_sync(0xFFFFFFFFu, d);
    int lane     = t & 31;
    int lanerank = __popc(mask & ((1u << lane) - 1));
    int cntm     = __popc(mask);
    int leader   = __ffs(mask) - 1;
    int wid      = t >> 5;

    int bpos = 0;
    #pragma unroll
    for (int w = 0; w < 32; w++) {
        if (wid == w && lane == leader) {
            bpos = offs[d];
            offs[d] = bpos + cntm;
        }
        __syncthreads();
    }
    bpos = __shfl_sync(0xFFFFFFFFu, bpos, leader);
    g_srcs[bpos + lanerank] = sv;
    g_dsts[bpos + lanerank] = d;
}

// ---------------------------------------------------------------------------
// Per-node projections + fp16 staging. One warp per row; each lane owns one
// float4. Writes ssrc/sdst and the half-converted x row (coalesced).
// ---------------------------------------------------------------------------
__global__ void k_dots(const float4* __restrict__ x4, const float4* __restrict__ W4,
                       const float* __restrict__ bias) {
    int wid  = (blockIdx.x * blockDim.x + threadIdx.x) >> 5;   // row in [0, B*N)
    int lane = threadIdx.x & 31;
    float4 xr = x4[(size_t)wid * 32 + lane];
    float4 ws = W4[lane];
    float4 wd = W4[32 + lane];

    // fp16 staged copy (4 halves per lane)
    __half2 h0 = __floats2half2_rn(xr.x, xr.y);
    __half2 h1 = __floats2half2_rn(xr.z, xr.w);
    uint2 pack;
    pack.x = *(unsigned int*)&h0;
    pack.y = *(unsigned int*)&h1;
    g_x16[(size_t)wid * 32 + lane] = pack;

    float a = xr.x * ws.x + xr.y * ws.y + xr.z * ws.z + xr.w * ws.w;
    float c = xr.x * wd.x + xr.y * wd.y + xr.z * wd.z + xr.w * wd.w;
    #pragma unroll
    for (int o = 16; o > 0; o >>= 1) {
        a += __shfl_xor_sync(0xFFFFFFFFu, a, o);
        c += __shfl_xor_sync(0xFFFFFFFFu, c, o);
    }
    if (lane == 0) {
        g_ssrc[wid] = a;
        g_sdst[wid] = c + bias[0];
    }
}

// ---------------------------------------------------------------------------
// Attention precompute: att[b, j] = sigmoid(ssrc[b, srcs[j]] + sdst[b, dsts[j]])
// Edge-parallel (786k threads) -> gather+MUFU latency fully hidden.
// ---------------------------------------------------------------------------
__global__ void k_att() {
    int t = blockIdx.x * blockDim.x + threadIdx.x;   // [0, B*EE)
    int b = t / EE;
    int j = t - b * EE;
    int s = g_srcs[j];
    int n = g_dsts[j];
    float z = g_ssrc[b * NN + s] + g_sdst[b * NN + n];
    g_att[t] = 1.0f / (1.0f + __expf(-z));
}

// ---------------------------------------------------------------------------
// Main gather kernel: one warp per (b, n); HALF-WARP per edge.
// fp16 row = 256B = 16 lanes x uint4, so lanes 0-15 take edge j and lanes
// 16-31 take edge j+1: ONE warp-wide LDG.128 fetches TWO edges' rows.
// Per-lane 8 fp32 accumulators; half-warps merged with shfl_xor(16) at end.
// Tail edge neutralized via gate a=0 + clamped safe index (no OOB).
// ---------------------------------------------------------------------------
__global__ void __launch_bounds__(256) k_main(float4* __restrict__ out4) {
    int w    = (blockIdx.x * blockDim.x + threadIdx.x) >> 5;   // (b,n) pair
    int lane = threadIdx.x & 31;
    int h = lane >> 4;          // which edge of the pair this lane serves
    int l = lane & 15;          // 16B chunk within the 256B row
    int b = w >> 12;            // / NN
    int n = w & (NN - 1);

    const uint4* xb   = (const uint4*)g_x16 + ((size_t)b * NN) * 16;
    const float* attb = g_att + (size_t)b * EE;
    int lo = g_offsets[n], hi = g_offsets[n + 1];

    float4 accA = make_float4(0.f, 0.f, 0.f, 0.f);   // features l*8 .. l*8+3
    float4 accB = make_float4(0.f, 0.f, 0.f, 0.f);   // features l*8+4 .. l*8+7

    for (int j = lo; j < hi; j += 2) {
        int  jj  = j + h;
        bool v   = jj < hi;
        int  idx = v ? jj : lo;             // safe in-range slot
        int   s  = g_srcs[idx];
        float a  = v ? attb[idx] : 0.0f;
        uint4 r  = xb[(size_t)s * 16 + l];  // one LDG.128 covers 2 edges/warp
        float2 f0 = __half22float2(*(__half2*)&r.x);
        float2 f1 = __half22float2(*(__half2*)&r.y);
        float2 f2 = __half22float2(*(__half2*)&r.z);
        float2 f3 = __half22float2(*(__half2*)&r.w);
        accA.x += f0.x * a; accA.y += f0.y * a; accA.z += f1.x * a; accA.w += f1.y * a;
        accB.x += f2.x * a; accB.y += f2.y * a; accB.z += f3.x * a; accB.w += f3.y * a;
    }

    // merge the two half-warps (lane (0,l) and (1,l) hold same feature slots)
    accA.x += __shfl_xor_sync(0xFFFFFFFFu, accA.x, 16);
    accA.y += __shfl_xor_sync(0xFFFFFFFFu, accA.y, 16);
    accA.z += __shfl_xor_sync(0xFFFFFFFFu, accA.z, 16);
    accA.w += __shfl_xor_sync(0xFFFFFFFFu, accA.w, 16);
    accB.x += __shfl_xor_sync(0xFFFFFFFFu, accB.x, 16);
    accB.y += __shfl_xor_sync(0xFFFFFFFFu, accB.y, 16);
    accB.z += __shfl_xor_sync(0xFFFFFFFFu, accB.z, 16);
    accB.w += __shfl_xor_sync(0xFFFFFFFFu, accB.w, 16);

    // store: lane (h,l) writes float4 at feature offset l*8 + h*4
    out4[(size_t)w * 32 + l * 2 + h] = (h == 0) ? accA : accB;
}

// ---------------------------------------------------------------------------
// Launch
// ---------------------------------------------------------------------------
extern "C" void kernel_launch(void* const* d_in, const int* in_sizes, int n_in,
                              void* d_out, int out_size) {
    const float* x    = (const float*)d_in[0];   // (B, N, D) f32
    const int*   ei   = (const int*)d_in[1];     // (2, E)    i32
    const float* W    = (const float*)d_in[2];   // (1, 2D)   f32
    const float* bias = (const float*)d_in[3];   // (1,)      f32
    float* out = (float*)d_out;                  // (B, N, D) f32

    const int* src = ei;        // edge_index[0]
    const int* dst = ei + EE;   // edge_index[1]

    kA_hist<<<NCHUNK, 1024>>>(dst);
    k_build2<<<NCHUNK, 1024>>>(src, dst);
    k_dots<<<BN / 8, 256>>>((const float4*)x, (const float4*)W, bias);
    k_att<<<(BB * EE) / 256, 256>>>();
    k_main<<<BN / 8, 256>>>((float4*)out);
}